// round 1
// baseline (speedup 1.0000x reference)
#include <cuda_runtime.h>
#include <cstdint>
#include <math.h>

// Problem dims
#define NTOK 8192
#define DIMD 1024
#define HID  4096
#define NEXP 8
#define NA   (NTOK*2)          // total assignments (top-2)

// GEMM tiling
#define BM 128
#define BN 128
#define BK 32
#define ASTR 36                // A smem row stride (pad: conflict-free + 16B aligned)
#define BSTR 136               // B smem row stride
#define MAXT 144               // >= 16384/128 + 8 worst-case M-tiles
#define GEMM_SMEM ((2*BM*ASTR + 2*BK*BSTR)*4)

// ---------------- device scratch (graph/alloc rules: __device__ globals) ----------------
__device__ float g_h[(size_t)(NA + BM) * HID];   // hidden activations (padded rows)
__device__ int   g_top_idx[NTOK * 2];
__device__ float g_top_gate[NTOK * 2];
__device__ int   g_count[NEXP];
__device__ int   g_offset[NEXP + 1];
__device__ int   g_cursor[NEXP];
__device__ float g_importance[NEXP];
__device__ int   g_tok[NA];
__device__ float g_gate[NA];
__device__ int   g_tile_e[MAXT];
__device__ int   g_tile_m[MAXT];
__device__ int   g_ntiles;

// ---------------- helpers ----------------
__device__ __forceinline__ uint32_t f2tf32(float f) {
    uint32_t u;
    asm("cvt.rna.tf32.f32 %0, %1;" : "=r"(u) : "f"(f));
    return u;
}

__device__ __forceinline__ void mma_tf32(float* c, const uint32_t* a, const uint32_t* b) {
    asm volatile(
        "mma.sync.aligned.m16n8k8.row.col.f32.tf32.tf32.f32 "
        "{%0,%1,%2,%3}, {%4,%5,%6,%7}, {%8,%9}, {%0,%1,%2,%3};\n"
        : "+f"(c[0]), "+f"(c[1]), "+f"(c[2]), "+f"(c[3])
        : "r"(a[0]), "r"(a[1]), "r"(a[2]), "r"(a[3]), "r"(b[0]), "r"(b[1]));
}

__device__ __forceinline__ void cpa16(void* smem_dst, const void* gsrc) {
    uint32_t d = (uint32_t)__cvta_generic_to_shared(smem_dst);
    asm volatile("cp.async.cg.shared.global [%0], [%1], 16;\n" :: "r"(d), "l"(gsrc));
}

// ---------------- init: zero output + per-call scratch ----------------
__global__ void init_kernel(float* __restrict__ out) {
    size_t i = (size_t)blockIdx.x * blockDim.x + threadIdx.x;
    float4 z = make_float4(0.f, 0.f, 0.f, 0.f);
    size_t n4 = (size_t)NTOK * DIMD / 4;
    size_t stride = (size_t)gridDim.x * blockDim.x;
    for (size_t j = i; j < n4; j += stride)
        reinterpret_cast<float4*>(out)[j] = z;
    if (blockIdx.x == 0 && threadIdx.x < NEXP) {
        g_count[threadIdx.x] = 0;
        g_importance[threadIdx.x] = 0.f;
    }
}

// ---------------- gating: one block per token ----------------
__global__ void gate_kernel(const float* __restrict__ x,
                            const float* __restrict__ Wg,
                            const float* __restrict__ bg) {
    const int t = blockIdx.x;
    const int tid = threadIdx.x;     // 128 threads
    const float* xr = x + (size_t)t * DIMD;

    float acc[NEXP];
#pragma unroll
    for (int e = 0; e < NEXP; e++) acc[e] = 0.f;

    for (int d = tid; d < DIMD; d += 128) {
        float xv = xr[d];
        const float* w = Wg + d * NEXP;
#pragma unroll
        for (int e = 0; e < NEXP; e++) acc[e] += xv * w[e];
    }
#pragma unroll
    for (int e = 0; e < NEXP; e++) {
#pragma unroll
        for (int o = 16; o > 0; o >>= 1)
            acc[e] += __shfl_down_sync(0xffffffffu, acc[e], o);
    }
    __shared__ float part[4][NEXP];
    if ((tid & 31) == 0) {
#pragma unroll
        for (int e = 0; e < NEXP; e++) part[tid >> 5][e] = acc[e];
    }
    __syncthreads();
    if (tid == 0) {
        float lg[NEXP];
#pragma unroll
        for (int e = 0; e < NEXP; e++)
            lg[e] = part[0][e] + part[1][e] + part[2][e] + part[3][e] + bg[e];
        // full softmax -> importance (aux loss)
        float mx = lg[0];
        for (int e = 1; e < NEXP; e++) mx = fmaxf(mx, lg[e]);
        float s = 0.f, p[NEXP];
#pragma unroll
        for (int e = 0; e < NEXP; e++) { p[e] = expf(lg[e] - mx); s += p[e]; }
        float inv = 1.f / s;
#pragma unroll
        for (int e = 0; e < NEXP; e++) atomicAdd(&g_importance[e], p[e] * inv);
        // top-2 (jax top_k tie-break: lowest index first; strict > keeps that)
        int i1 = 0;
        for (int e = 1; e < NEXP; e++) if (lg[e] > lg[i1]) i1 = e;
        int i2 = -1;
        for (int e = 0; e < NEXP; e++)
            if (e != i1 && (i2 < 0 || lg[e] > lg[i2])) i2 = e;
        float e2 = expf(lg[i2] - lg[i1]);   // <= 1
        float g1 = 1.f / (1.f + e2);
        float g2 = e2 * g1;
        g_top_idx[2 * t] = i1;  g_top_idx[2 * t + 1] = i2;
        g_top_gate[2 * t] = g1; g_top_gate[2 * t + 1] = g2;
        atomicAdd(&g_count[i1], 1);
        atomicAdd(&g_count[i2], 1);
    }
}

// ---------------- plan: offsets + tile descriptors ----------------
__global__ void plan_kernel() {
    if (threadIdx.x == 0 && blockIdx.x == 0) {
        int off = 0, nt = 0;
        for (int e = 0; e < NEXP; e++) {
            g_offset[e] = off;
            g_cursor[e] = 0;
            int c = g_count[e];
            off += c;
            int mt = (c + BM - 1) / BM;
            for (int i = 0; i < mt; i++) {
                g_tile_e[nt] = e;
                g_tile_m[nt] = i * BM;
                nt++;
            }
        }
        g_offset[NEXP] = off;
        g_ntiles = nt;
    }
}

// ---------------- scatter: build per-expert token lists ----------------
__global__ void scatter_kernel() {
    int t = blockIdx.x * blockDim.x + threadIdx.x;
    if (t < NTOK) {
#pragma unroll
        for (int k = 0; k < 2; k++) {
            int e = g_top_idx[2 * t + k];
            int p = atomicAdd(&g_cursor[e], 1);
            int s = g_offset[e] + p;
            g_tok[s] = t;
            g_gate[s] = g_top_gate[2 * t + k];
        }
    }
}

// ---------------- grouped GEMM (TF32 mma.sync, 2-stage cp.async) ----------------
// FIRST:  h = relu(gather(x) @ W1[e] + b1[e])        K=1024, N=4096
// !FIRST: out[tok] += gate * (h @ W2[e] + b2[e])     K=4096, N=1024
template<bool FIRST>
__global__ void __launch_bounds__(256)
moe_gemm(const float* __restrict__ x,
         const float* __restrict__ W1, const float* __restrict__ b1,
         const float* __restrict__ W2, const float* __restrict__ b2,
         float* __restrict__ out)
{
    const int tix = blockIdx.y;
    if (tix >= g_ntiles) return;
    const int e = g_tile_e[tix];
    const int mstart = g_tile_m[tix];
    const int off = g_offset[e];
    const int cnt = g_count[e];
    const int n0 = blockIdx.x * BN;

    const int K   = FIRST ? DIMD : HID;
    const int ldb = FIRST ? HID : DIMD;
    const float* Bg = FIRST ? (W1 + (size_t)e * DIMD * HID)
                            : (W2 + (size_t)e * HID * DIMD);

    extern __shared__ float sm[];
    float* As = sm;                       // [2][BM][ASTR]
    float* Bs = sm + 2 * BM * ASTR;       // [2][BK][BSTR]
    __shared__ int   s_tok[BM];
    __shared__ float s_gate[BM];

    const int tid = threadIdx.x;
    for (int r = tid; r < BM; r += 256) {
        int gr = mstart + r;
        bool v = gr < cnt;
        s_tok[r]  = v ? g_tok[off + gr]  : 0;
        s_gate[r] = v ? g_gate[off + gr] : 0.f;
    }
    __syncthreads();

    const int warp = tid >> 5, lane = tid & 31;
    const int wm = warp >> 1, wn = warp & 1;     // 4x2 warp grid, warp tile 32x64
    const int ar  = tid >> 3;                    // 0..31
    const int ac4 = (tid & 7) << 2;              // 0,4,..,28

    float acc[2][8][4];
#pragma unroll
    for (int i = 0; i < 2; i++)
#pragma unroll
        for (int j = 0; j < 8; j++)
#pragma unroll
            for (int q = 0; q < 4; q++) acc[i][j][q] = 0.f;

    auto load_stage = [&](int buf, int k0) {
#pragma unroll
        for (int j = 0; j < 4; j++) {
            int r = ar + j * 32;
            const float* src;
            if constexpr (FIRST)
                src = x + (size_t)s_tok[r] * DIMD + (k0 + ac4);
            else
                src = g_h + (size_t)(off + mstart + r) * HID + (k0 + ac4);
            cpa16(&As[buf * BM * ASTR + r * ASTR + ac4], src);
        }
#pragma unroll
        for (int j = 0; j < 4; j++) {
            int c4 = ac4 + j * 32;
            cpa16(&Bs[buf * BK * BSTR + ar * BSTR + c4],
                  Bg + (size_t)(k0 + ar) * ldb + n0 + c4);
        }
    };

    load_stage(0, 0);
    asm volatile("cp.async.commit_group;\n");

    const int KIT = K / BK;
    for (int kit = 0; kit < KIT; kit++) {
        int cur = kit & 1;
        if (kit + 1 < KIT) load_stage(cur ^ 1, (kit + 1) * BK);
        asm volatile("cp.async.commit_group;\n");
        asm volatile("cp.async.wait_group 1;\n");
        __syncthreads();

        const float* Ab = As + cur * BM * ASTR;
        const float* Bb = Bs + cur * BK * BSTR;
#pragma unroll
        for (int ks = 0; ks < 4; ks++) {
            uint32_t af[2][4], bf[8][2];
            int arow = wm * 32 + (lane >> 2);
            int acol = ks * 8 + (lane & 3);
#pragma unroll
            for (int mi = 0; mi < 2; mi++) {
                int r = arow + mi * 16;
                af[mi][0] = f2tf32(Ab[r * ASTR + acol]);
                af[mi][1] = f2tf32(Ab[(r + 8) * ASTR + acol]);
                af[mi][2] = f2tf32(Ab[r * ASTR + acol + 4]);
                af[mi][3] = f2tf32(Ab[(r + 8) * ASTR + acol + 4]);
            }
            int bro = ks * 8 + (lane & 3);
#pragma unroll
            for (int ni = 0; ni < 8; ni++) {
                int c = wn * 64 + ni * 8 + (lane >> 2);
                bf[ni][0] = f2tf32(Bb[bro * BSTR + c]);
                bf[ni][1] = f2tf32(Bb[(bro + 4) * BSTR + c]);
            }
#pragma unroll
            for (int mi = 0; mi < 2; mi++)
#pragma unroll
                for (int ni = 0; ni < 8; ni++)
                    mma_tf32(acc[mi][ni], af[mi], bf[ni]);
        }
        __syncthreads();
    }

    // epilogue
#pragma unroll
    for (int ni = 0; ni < 8; ni++) {
        int c = n0 + wn * 64 + ni * 8 + ((lane & 3) << 1);
        float2 bias;
        if constexpr (FIRST) bias = *reinterpret_cast<const float2*>(b1 + (size_t)e * HID + c);
        else                 bias = *reinterpret_cast<const float2*>(b2 + (size_t)e * DIMD + c);
#pragma unroll
        for (int mi = 0; mi < 2; mi++) {
            int rbase = wm * 32 + mi * 16 + (lane >> 2);
#pragma unroll
            for (int h = 0; h < 2; h++) {
                int r = rbase + h * 8;
                int gr = mstart + r;
                if (gr < cnt) {
                    float vx = acc[mi][ni][2 * h + 0] + bias.x;
                    float vy = acc[mi][ni][2 * h + 1] + bias.y;
                    if constexpr (FIRST) {
                        float2 v2 = make_float2(fmaxf(vx, 0.f), fmaxf(vy, 0.f));
                        *reinterpret_cast<float2*>(g_h + (size_t)(off + gr) * HID + c) = v2;
                    } else {
                        float g = s_gate[r];
                        int   tk = s_tok[r];
                        atomicAdd(out + (size_t)tk * DIMD + c,     vx * g);
                        atomicAdd(out + (size_t)tk * DIMD + c + 1, vy * g);
                    }
                }
            }
        }
    }
}

// ---------------- aux loss ----------------
__global__ void aux_kernel(float* __restrict__ out, int out_size) {
    if (threadIdx.x == 0 && out_size > NTOK * DIMD) {
        float m = 0.f;
        for (int e = 0; e < NEXP; e++) m += g_importance[e];
        m /= (float)NEXP;
        float v = 0.f;
        for (int e = 0; e < NEXP; e++) {
            float d = g_importance[e] - m;
            v += d * d;
        }
        v /= (float)(NEXP - 1);     // ddof=1
        float cv = sqrtf(v) / (m + 1e-8f);
        out[NTOK * DIMD] = cv * cv;
    }
}

// ---------------- launch ----------------
extern "C" void kernel_launch(void* const* d_in, const int* in_sizes, int n_in,
                              void* d_out, int out_size) {
    (void)in_sizes; (void)n_in;
    const float* x  = (const float*)d_in[0];
    const float* W1 = (const float*)d_in[1];
    const float* b1 = (const float*)d_in[2];
    const float* W2 = (const float*)d_in[3];
    const float* b2 = (const float*)d_in[4];
    const float* Wg = (const float*)d_in[5];
    const float* bg = (const float*)d_in[6];
    float* out = (float*)d_out;

    cudaFuncSetAttribute(moe_gemm<true>,  cudaFuncAttributeMaxDynamicSharedMemorySize, GEMM_SMEM);
    cudaFuncSetAttribute(moe_gemm<false>, cudaFuncAttributeMaxDynamicSharedMemorySize, GEMM_SMEM);

    init_kernel<<<256, 256>>>(out);
    gate_kernel<<<NTOK, 128>>>(x, Wg, bg);
    plan_kernel<<<1, 32>>>();
    scatter_kernel<<<NTOK / 256, 256>>>();
    moe_gemm<true ><<<dim3(HID / BN,  MAXT), 256, GEMM_SMEM>>>(x, W1, b1, W2, b2, out);
    moe_gemm<false><<<dim3(DIMD / BN, MAXT), 256, GEMM_SMEM>>>(x, W1, b1, W2, b2, out);
    aux_kernel<<<1, 32>>>(out, out_size);
}